// round 10
// baseline (speedup 1.0000x reference)
#include <cuda_runtime.h>
#include <math.h>

// BalancedAveragedHausdorffLoss, single fused kernel, v6.
// 128 blocks: (item, which, half). Row masks via ballot (no atomics),
// horizontal bitdist phase 1, batched vote-free vertical scan phase 2
// (warp-uniform radius bound, 16 independent LDS+min per iteration).
// Finalize parallelized across warp 0 of the last block.

#define ITEMS 32
#define Wdim  64
#define HW    4096
#define GINF  127   // GINF^2 = 16129

__device__ float        g_terms[4 * ITEMS];   // [item*4 + which*2 + half]
__device__ int          g_cnt[4 * ITEMS];     // [item*4 + {nt0,nt1,np0,np1}]
__device__ unsigned int g_done;               // 0 at start; reset by last block

// nearest-set-bit distance from position p in 64-bit mask M (GINF if none)
__device__ __forceinline__ int bitdist(unsigned long long M, int p) {
    unsigned long long U = M >> p;
    unsigned long long V = M << (63 - p);
    int dDown = U ? (__ffsll((long long)U) - 1) : GINF;
    int dUp   = V ? __clzll((long long)V)      : GINF;
    return min(dDown, dUp);
}

__global__ __launch_bounds__(256)
void bahl_fused_kernel(const float* __restrict__ pred,
                       const float* __restrict__ target,
                       float* __restrict__ out)
{
    __shared__ unsigned long long rmask[Wdim];   // src-mask bits over y, per row x
    __shared__ int   h2s[HW];                    // squared horizontal distance [x][y]
    __shared__ float sacc[8];
    __shared__ int   ssc[8], sdc[8];
    __shared__ int   sIsLast;

    const int bi    = blockIdx.x;
    const int item  = bi >> 2;
    const int which = (bi >> 1) & 1;
    const int half  = bi & 1;
    const int tid   = threadIdx.x;

    const float* pb = pred   + item * HW;
    const float* tb = target + item * HW;
    const float* srcA = which ? pb : tb;   // which==0: src = target
    const float* dstA = which ? tb : pb;
    const bool srcIsTarget = (which == 0);
    const float THR = 0.30001f;

    // --- Loop A: full src scan -> rowmask via ballot + src count on our half
    int srcCount = 0;
    #pragma unroll
    for (int k = 0; k < 16; k++) {
        const int pix = tid + k * 256;
        float v = srcA[pix];
        bool bit = srcIsTarget ? (v != 0.0f) : (fabsf(v - 1.0f) <= THR);
        unsigned bal = __ballot_sync(0xffffffffu, bit);
        if ((tid & 31) == 0) ((unsigned*)rmask)[pix >> 5] = bal;
        if ((pix >> 11) == half) srcCount += bit ? 1 : 0;
    }

    // --- Loop B: dst scan on our half -> dst bits + count ---------------
    const int pbase = half * 2048;
    int dstCount = 0;
    unsigned dmaskbits = 0;
    #pragma unroll
    for (int j = 0; j < 8; j++) {
        const int pix = pbase + tid + j * 256;
        float v = dstA[pix];
        bool bit = srcIsTarget ? (fabsf(v - 1.0f) <= THR) : (v != 0.0f);
        dmaskbits |= (bit ? 1u : 0u) << j;
        dstCount += bit ? 1 : 0;
    }
    __syncthreads();   // rmask complete

    // --- Phase 1: squared horizontal distances h2[x][y] ------------------
    #pragma unroll
    for (int k = 0; k < 16; k++) {
        const int idx = tid + k * 256;
        const int x = idx >> 6, y = idx & 63;
        int h = bitdist(rmask[x], y);
        h2s[idx] = h * h;
    }
    __syncthreads();

    // --- Phase 2: batched vertical scan, warp-uniform radius bound -------
    // Thread owns fixed column y and rows x0 + 4j (j = 0..7).
    const int y  = tid & 63;
    const int x0 = half * 32 + (tid >> 6);
    int dmin[8];
    #pragma unroll
    for (int j = 0; j < 8; j++) dmin[j] = h2s[(x0 + 4 * j) * Wdim + y];

    int m = 0;
    #pragma unroll
    for (int j = 0; j < 8; j++) m = max(m, dmin[j]);
    #pragma unroll
    for (int o = 16; o > 0; o >>= 1)
        m = max(m, __shfl_xor_sync(0xffffffffu, m, o));
    // Since dmin only shrinks, radii with r^2 >= m can never improve any lane.

    #pragma unroll 1
    for (int r = 1; r * r < m && r < Wdim; r++) {
        const int rr = r * r;
        #pragma unroll
        for (int j = 0; j < 8; j++) {
            const int xj = x0 + 4 * j;
            const int xu = xj - r, xd = xj + r;
            if (xu >= 0)   dmin[j] = min(dmin[j], rr + h2s[xu * Wdim + y]);
            if (xd < Wdim) dmin[j] = min(dmin[j], rr + h2s[xd * Wdim + y]);
        }
    }

    float acc = 0.0f;
    #pragma unroll
    for (int j = 0; j < 8; j++)
        if ((dmaskbits >> j) & 1u) acc += sqrtf((float)dmin[j]);

    // --- Block reduction -------------------------------------------------
    #pragma unroll
    for (int o = 16; o > 0; o >>= 1) {
        acc      += __shfl_xor_sync(0xffffffffu, acc,      o);
        srcCount += __shfl_xor_sync(0xffffffffu, srcCount, o);
        dstCount += __shfl_xor_sync(0xffffffffu, dstCount, o);
    }
    const int wid = tid >> 5, lid = tid & 31;
    if (lid == 0) { sacc[wid] = acc; ssc[wid] = srcCount; sdc[wid] = dstCount; }
    __syncthreads();

    if (tid == 0) {
        float a = 0.0f; int s = 0, d = 0;
        #pragma unroll
        for (int w = 0; w < 8; w++) { a += sacc[w]; s += ssc[w]; d += sdc[w]; }
        g_terms[item * 4 + which * 2 + half] = a;
        if (which == 0) {                       // src=target, dst=pred
            g_cnt[item * 4 + half]     = s;     // n_t (this half)
            g_cnt[item * 4 + 2 + half] = d;     // n_p (this half)
        }
        __threadfence();
        unsigned old = atomicAdd(&g_done, 1u);
        sIsLast = (old == 4 * ITEMS - 1) ? 1 : 0;
    }
    __syncthreads();

    // --- Parallel finalize in last block: lane i handles item i ----------
    if (sIsLast && tid < 32) {
        __threadfence();
        volatile float* vt = g_terms;
        volatile int*   vc = g_cnt;
        const int i = tid;
        float t1 = vt[4 * i]     + vt[4 * i + 1];
        float t2 = vt[4 * i + 2] + vt[4 * i + 3];
        int   nt = vc[4 * i]     + vc[4 * i + 1];
        int   np = vc[4 * i + 2] + vc[4 * i + 3];
        float v = (nt > 0 && np > 0) ? (t1 + t2) / (2.0f * (float)nt) : 0.0f;
        #pragma unroll
        for (int o = 16; o > 0; o >>= 1)
            v += __shfl_xor_sync(0xffffffffu, v, o);
        if (tid == 0) {
            out[0] = v / (float)ITEMS;
            __threadfence();
            g_done = 0;                   // reset for next graph replay
        }
    }
}

extern "C" void kernel_launch(void* const* d_in, const int* in_sizes, int n_in,
                              void* d_out, int out_size)
{
    const float* pred   = (const float*)d_in[0];
    const float* target = (const float*)d_in[1];
    float* out = (float*)d_out;
    (void)in_sizes; (void)n_in; (void)out_size;

    bahl_fused_kernel<<<4 * ITEMS, 256>>>(pred, target, out);
}

// round 11
// speedup vs baseline: 1.5378x; 1.5378x over previous
#include <cuda_runtime.h>
#include <math.h>

// BalancedAveragedHausdorffLoss, single fused kernel, v7.
// = v5 body (best measured: per-pixel early-exit phase 2) with 512-thread
// blocks to halve per-thread latency chains. 128 blocks (item, which, half).
// Finalize parallelized across warp 0 of the last block.

#define ITEMS 32
#define Wdim  64
#define HW    4096
#define GINF  127   // GINF^2 = 16129

#define NT    512
#define NWARP 16

__device__ float        g_terms[4 * ITEMS];   // [item*4 + which*2 + half]
__device__ int          g_cnt[4 * ITEMS];     // [item*4 + {nt0,nt1,np0,np1}]
__device__ unsigned int g_done;               // 0 at start; reset by last block

// nearest-set-bit distance from position p in 64-bit mask M (GINF if none)
__device__ __forceinline__ int bitdist(unsigned long long M, int p) {
    unsigned long long U = M >> p;
    unsigned long long V = M << (63 - p);
    int dDown = U ? (__ffsll((long long)U) - 1) : GINF;
    int dUp   = V ? __clzll((long long)V)      : GINF;
    return min(dDown, dUp);
}

__global__ __launch_bounds__(NT)
void bahl_fused_kernel(const float* __restrict__ pred,
                       const float* __restrict__ target,
                       float* __restrict__ out)
{
    __shared__ unsigned long long rmask[Wdim];   // src-mask bits over y, per row x
    __shared__ int   h2s[HW];                    // squared horizontal distance [x][y]
    __shared__ float sacc[NWARP];
    __shared__ int   ssc[NWARP], sdc[NWARP];
    __shared__ int   sIsLast;

    const int bi    = blockIdx.x;
    const int item  = bi >> 2;
    const int which = (bi >> 1) & 1;
    const int half  = bi & 1;
    const int tid   = threadIdx.x;

    const float* pb = pred   + item * HW;
    const float* tb = target + item * HW;
    const float* srcA = which ? pb : tb;   // which==0: src = target
    const float* dstA = which ? tb : pb;
    const bool srcIsTarget = (which == 0);
    const float THR = 0.30001f;

    // --- Loop A: full src scan -> rowmask via ballot + src count on our half
    int srcCount = 0;
    #pragma unroll
    for (int k = 0; k < 8; k++) {
        const int pix = tid + k * NT;
        float v = srcA[pix];
        bool bit = srcIsTarget ? (v != 0.0f) : (fabsf(v - 1.0f) <= THR);
        unsigned bal = __ballot_sync(0xffffffffu, bit);
        if ((tid & 31) == 0) ((unsigned*)rmask)[pix >> 5] = bal;
        if ((pix >> 11) == half) srcCount += bit ? 1 : 0;
    }

    // --- Loop B: dst scan on our half -> dst bits + count ---------------
    const int pbase = half * 2048;
    int dstCount = 0;
    unsigned dmaskbits = 0;
    #pragma unroll
    for (int j = 0; j < 4; j++) {
        const int pix = pbase + tid + j * NT;
        float v = dstA[pix];
        bool bit = srcIsTarget ? (fabsf(v - 1.0f) <= THR) : (v != 0.0f);
        dmaskbits |= (bit ? 1u : 0u) << j;
        dstCount += bit ? 1 : 0;
    }
    __syncthreads();   // rmask complete

    // --- Phase 1: squared horizontal distances h2[x][y] ------------------
    // 32 consecutive pixels share a row -> rmask[x] is an LDS broadcast.
    #pragma unroll
    for (int k = 0; k < 8; k++) {
        const int idx = tid + k * NT;
        const int x = idx >> 6, y = idx & 63;
        int h = bitdist(rmask[x], y);
        h2s[idx] = h * h;
    }
    __syncthreads();

    // --- Phase 2: per-pixel adaptive vertical scan (warp-vote early exit)
    float acc = 0.0f;
    #pragma unroll
    for (int j = 0; j < 4; j++) {
        const int pix = pbase + tid + j * NT;
        const int x = pix >> 6;
        const int y = pix & 63;
        int dmin = h2s[pix];                     // r = 0 (own row)
        #pragma unroll 1
        for (int r = 1; r < Wdim; r++) {
            if (!__any_sync(0xffffffffu, r * r < dmin)) break;
            const int rr = r * r;
            const int xu = x - r, xd = x + r;
            if (xu >= 0)   dmin = min(dmin, rr + h2s[xu * Wdim + y]);
            if (xd < Wdim) dmin = min(dmin, rr + h2s[xd * Wdim + y]);
        }
        if ((dmaskbits >> j) & 1u) acc += sqrtf((float)dmin);
    }

    // --- Block reduction -------------------------------------------------
    #pragma unroll
    for (int o = 16; o > 0; o >>= 1) {
        acc      += __shfl_xor_sync(0xffffffffu, acc,      o);
        srcCount += __shfl_xor_sync(0xffffffffu, srcCount, o);
        dstCount += __shfl_xor_sync(0xffffffffu, dstCount, o);
    }
    const int wid = tid >> 5, lid = tid & 31;
    if (lid == 0) { sacc[wid] = acc; ssc[wid] = srcCount; sdc[wid] = dstCount; }
    __syncthreads();

    if (tid == 0) {
        float a = 0.0f; int s = 0, d = 0;
        #pragma unroll
        for (int w = 0; w < NWARP; w++) { a += sacc[w]; s += ssc[w]; d += sdc[w]; }
        g_terms[item * 4 + which * 2 + half] = a;
        if (which == 0) {                       // src=target, dst=pred
            g_cnt[item * 4 + half]     = s;     // n_t (this half)
            g_cnt[item * 4 + 2 + half] = d;     // n_p (this half)
        }
        __threadfence();
        unsigned old = atomicAdd(&g_done, 1u);
        sIsLast = (old == 4 * ITEMS - 1) ? 1 : 0;
    }
    __syncthreads();

    // --- Parallel finalize in last block: lane i handles item i ----------
    if (sIsLast && tid < 32) {
        __threadfence();
        volatile float* vt = g_terms;
        volatile int*   vc = g_cnt;
        const int i = tid;
        float t1 = vt[4 * i]     + vt[4 * i + 1];
        float t2 = vt[4 * i + 2] + vt[4 * i + 3];
        int   nt = vc[4 * i]     + vc[4 * i + 1];
        int   np = vc[4 * i + 2] + vc[4 * i + 3];
        float v = (nt > 0 && np > 0) ? (t1 + t2) / (2.0f * (float)nt) : 0.0f;
        #pragma unroll
        for (int o = 16; o > 0; o >>= 1)
            v += __shfl_xor_sync(0xffffffffu, v, o);
        if (tid == 0) {
            out[0] = v / (float)ITEMS;
            __threadfence();
            g_done = 0;                   // reset for next graph replay
        }
    }
}

extern "C" void kernel_launch(void* const* d_in, const int* in_sizes, int n_in,
                              void* d_out, int out_size)
{
    const float* pred   = (const float*)d_in[0];
    const float* target = (const float*)d_in[1];
    float* out = (float*)d_out;
    (void)in_sizes; (void)n_in; (void)out_size;

    bahl_fused_kernel<<<4 * ITEMS, NT>>>(pred, target, out);
}